// round 14
// baseline (speedup 1.0000x reference)
#include <cuda_runtime.h>
#include <cmath>
#include <cstdint>

#define NB 8
#define LL 1024
#define EE 512

// ---------------- scratch (static __device__, no allocs) ----------------
__device__ float g_p[4][NB * LL * EE];   // proj qA,kA,qB,kB (tf32-valued fp32)
__device__ float g_scores[32][LL * LL];  // [combo*8+n][q][k]

// ---------------- PTX helpers ----------------
__device__ __forceinline__ uint32_t smem_u32(const void* p) {
    uint32_t a;
    asm("{ .reg .u64 t; cvta.to.shared.u64 t, %1; cvt.u32.u64 %0, t; }"
        : "=r"(a) : "l"(p));
    return a;
}
__device__ __forceinline__ uint32_t f2tf32(float x) {
    uint32_t u;
    asm("cvt.rna.tf32.f32 %0, %1;" : "=r"(u) : "f"(x));
    return u;
}
#define CP_ASYNC16(sa, gp) \
    asm volatile("cp.async.cg.shared.global [%0], [%1], 16;" :: "r"(sa), "l"(gp) : "memory")
#define CP_COMMIT() asm volatile("cp.async.commit_group;" ::: "memory")
#define CP_WAIT1()  asm volatile("cp.async.wait_group 1;" ::: "memory")
#define CP_WAIT0()  asm volatile("cp.async.wait_group 0;" ::: "memory")

__device__ __forceinline__ void mma_tf32(float* d, const uint32_t* a,
                                         const uint32_t* b) {
    asm volatile(
        "mma.sync.aligned.m16n8k8.row.col.f32.tf32.tf32.f32 "
        "{%0,%1,%2,%3}, {%4,%5,%6,%7}, {%8,%9}, {%0,%1,%2,%3};"
        : "+f"(d[0]), "+f"(d[1]), "+f"(d[2]), "+f"(d[3])
        : "r"(a[0]), "r"(a[1]), "r"(a[2]), "r"(a[3]), "r"(b[0]), "r"(b[1]));
}

// ---------------- GEMM core: D(128x256,f32) = A(128xK) * B(256xK)^T ------
// 256 threads, 8 warps (2m x 4n), each warp 64x64 via 4x8 grid of m16n8k8.
// K = 512, chunk 32, double-buffered cp.async. ROUND: cvt.rna fragments.
#define PITCH 36
#define KC 32
#define AROWS 128
#define BROWS 256
#define FA (AROWS * PITCH)
#define FB (BROWS * PITCH)
#define FBUF (FA + FB)
#define SMEM_SZ (2 * FBUF * 4)   // 110592 bytes

__device__ __forceinline__ void load_chunk(const float* __restrict__ pa,
                                           const float* __restrict__ pb,
                                           int k0, uint32_t sa, uint32_t sb,
                                           int m0, int n0, int tid) {
    // A: units 0..1023 (128 rows x 8 segs); B: units 1024..3071 (256 rows x 8)
#pragma unroll
    for (int i = 0; i < 4; i++) {
        const int u = tid + i * 256;
        const int row = u >> 3, seg = u & 7;
        CP_ASYNC16(sa + (uint32_t)(row * PITCH + seg * 4) * 4u,
                   pa + (size_t)(m0 + row) * EE + k0 + seg * 4);
    }
#pragma unroll
    for (int i = 0; i < 8; i++) {
        const int u = tid + i * 256;
        const int row = u >> 3, seg = u & 7;
        CP_ASYNC16(sb + (uint32_t)(row * PITCH + seg * 4) * 4u,
                   pb + (size_t)(n0 + row) * EE + k0 + seg * 4);
    }
    CP_COMMIT();
}

template <bool ROUND>
__device__ __forceinline__ void gemm_core(const float* __restrict__ A,
                                          const float* __restrict__ B,
                                          int m0, int n0,
                                          float acc[4][8][4]) {
    extern __shared__ float smem[];
    float* As[2] = {smem, smem + FBUF};
    float* Bs[2] = {smem + FA, smem + FBUF + FA};
    const uint32_t sAu[2] = {smem_u32(As[0]), smem_u32(As[1])};
    const uint32_t sBu[2] = {smem_u32(Bs[0]), smem_u32(Bs[1])};

    const int tid = threadIdx.x;
    const int lane = tid & 31;
    const int wid = tid >> 5;
    const int wm = (wid & 1) * 64;   // warp m offset
    const int wn = (wid >> 1) * 64;  // warp n offset
    const int g = lane >> 2;         // group id 0..7
    const int c = lane & 3;          // 0..3

#pragma unroll
    for (int mt = 0; mt < 4; mt++)
#pragma unroll
        for (int nt = 0; nt < 8; nt++)
#pragma unroll
            for (int j = 0; j < 4; j++) acc[mt][nt][j] = 0.f;

    load_chunk(A, B, 0, sAu[0], sBu[0], m0, n0, tid);

    const int NCH = EE / KC;  // 16
    for (int ch = 0; ch < NCH; ch++) {
        const int buf = ch & 1;
        if (ch + 1 < NCH)
            load_chunk(A, B, (ch + 1) * KC, sAu[buf ^ 1], sBu[buf ^ 1], m0, n0, tid);
        if (ch + 1 < NCH) { CP_WAIT1(); } else { CP_WAIT0(); }
        __syncthreads();

        const float* sA = As[buf];
        const float* sB = Bs[buf];
#pragma unroll
        for (int ks = 0; ks < KC / 8; ks++) {
            const int k = ks * 8;
            uint32_t af[4][4];
#pragma unroll
            for (int mt = 0; mt < 4; mt++) {
                const float* p = sA + (size_t)(wm + mt * 16 + g) * PITCH + k + c;
                af[mt][0] = __float_as_uint(p[0]);
                af[mt][1] = __float_as_uint(p[8 * PITCH]);
                af[mt][2] = __float_as_uint(p[4]);
                af[mt][3] = __float_as_uint(p[8 * PITCH + 4]);
                if (ROUND) {
#pragma unroll
                    for (int j = 0; j < 4; j++)
                        af[mt][j] = f2tf32(__uint_as_float(af[mt][j]));
                }
            }
            uint32_t bf[8][2];
#pragma unroll
            for (int nt = 0; nt < 8; nt++) {
                const float* p = sB + (size_t)(wn + nt * 8 + g) * PITCH + k + c;
                bf[nt][0] = __float_as_uint(p[0]);
                bf[nt][1] = __float_as_uint(p[4]);
                if (ROUND) {
                    bf[nt][0] = f2tf32(__uint_as_float(bf[nt][0]));
                    bf[nt][1] = f2tf32(__uint_as_float(bf[nt][1]));
                }
            }
#pragma unroll
            for (int mt = 0; mt < 4; mt++)
#pragma unroll
                for (int nt = 0; nt < 8; nt++)
                    mma_tf32(acc[mt][nt], af[mt], bf[nt]);
        }
        __syncthreads();
    }
}

// ---------------- projections: q/k = x @ W^T + b ----------------
// Reads raw fp32 inputs; rounds fragments to tf32 in-register; writes
// tf32-valued fp32 projections.
__global__ void __launch_bounds__(256) proj_mma(
    const float* __restrict__ mA, const float* __restrict__ mB,
    const float* __restrict__ WqA, const float* __restrict__ bqA,
    const float* __restrict__ WkA, const float* __restrict__ bkA,
    const float* __restrict__ WqB, const float* __restrict__ bqB,
    const float* __restrict__ WkB, const float* __restrict__ bkB) {
    const int cc = blockIdx.z;
    const int m0 = blockIdx.y * 128, n0 = blockIdx.x * 256;
    const float* X = (cc < 2) ? mA : mB;
    const float* W = (cc == 0) ? WqA : (cc == 1) ? WkA : (cc == 2) ? WqB : WkB;
    const float* bias = (cc == 0) ? bqA : (cc == 1) ? bkA : (cc == 2) ? bqB : bkB;

    float acc[4][8][4];
    gemm_core<true>(X, W, m0, n0, acc);

    const int lane = threadIdx.x & 31, wid = threadIdx.x >> 5;
    const int wm = (wid & 1) * 64, wn = (wid >> 1) * 64;
    const int g = lane >> 2, c2 = (lane & 3) * 2;
    float* out = g_p[cc];
#pragma unroll
    for (int nt = 0; nt < 8; nt++) {
        const int n = n0 + wn + nt * 8 + c2;
        const float bv0 = __ldg(&bias[n]);
        const float bv1 = __ldg(&bias[n + 1]);
#pragma unroll
        for (int mt = 0; mt < 4; mt++) {
#pragma unroll
            for (int h = 0; h < 2; h++) {
                const int m = m0 + wm + mt * 16 + h * 8 + g;
                uint2 o;
                o.x = f2tf32(acc[mt][nt][2 * h] + bv0);
                o.y = f2tf32(acc[mt][nt][2 * h + 1] + bv1);
                *(uint2*)&out[(size_t)m * EE + n] = o;
            }
        }
    }
}

// ---------------- scores: S = q @ k^T * inv_scale ----------------
__global__ void __launch_bounds__(256) score_mma(float scale) {
    const int z = blockIdx.z, cc = z >> 3, nn = z & 7;
    const int qsel = (cc < 2) ? 0 : 2;
    const int ksel = (cc == 0 || cc == 3) ? 1 : 3;
    const size_t off = (size_t)nn * LL * EE;
    const int m0 = blockIdx.y * 128, n0 = blockIdx.x * 256;

    float acc[4][8][4];
    gemm_core<false>(g_p[qsel] + off, g_p[ksel] + off, m0, n0, acc);

    const int lane = threadIdx.x & 31, wid = threadIdx.x >> 5;
    const int wm = (wid & 1) * 64, wn = (wid >> 1) * 64;
    const int g = lane >> 2, c2 = (lane & 3) * 2;
    float* out = g_scores[z];
#pragma unroll
    for (int mt = 0; mt < 4; mt++) {
#pragma unroll
        for (int h = 0; h < 2; h++) {
            const int m = m0 + wm + mt * 16 + h * 8 + g;
            float* row = out + (size_t)m * LL;
#pragma unroll
            for (int nt = 0; nt < 8; nt++) {
                float2 v;
                v.x = acc[mt][nt][2 * h] * scale;
                v.y = acc[mt][nt][2 * h + 1] * scale;
                *(float2*)&row[n0 + wn + nt * 8 + c2] = v;
            }
        }
    }
}

// ---------------- block reductions ----------------
__device__ __forceinline__ float blockReduceMax(float v, float* red) {
#pragma unroll
    for (int o = 16; o > 0; o >>= 1) v = fmaxf(v, __shfl_xor_sync(0xffffffffu, v, o));
    const int w = threadIdx.x >> 5;
    if ((threadIdx.x & 31) == 0) red[w] = v;
    __syncthreads();
    if (threadIdx.x < 8) {
        float t = red[threadIdx.x];
#pragma unroll
        for (int o = 4; o > 0; o >>= 1) t = fmaxf(t, __shfl_xor_sync(0xffu, t, o));
        if (threadIdx.x == 0) red[0] = t;
    }
    __syncthreads();
    v = red[0];
    __syncthreads();
    return v;
}
__device__ __forceinline__ float blockReduceSum(float v, float* red) {
#pragma unroll
    for (int o = 16; o > 0; o >>= 1) v += __shfl_xor_sync(0xffffffffu, v, o);
    const int w = threadIdx.x >> 5;
    if ((threadIdx.x & 31) == 0) red[w] = v;
    __syncthreads();
    if (threadIdx.x < 8) {
        float t = red[threadIdx.x];
#pragma unroll
        for (int o = 4; o > 0; o >>= 1) t += __shfl_xor_sync(0xffu, t, o);
        if (threadIdx.x == 0) red[0] = t;
    }
    __syncthreads();
    v = red[0];
    __syncthreads();
    return v;
}

// ---------------- softmax + mean over N, write [2048,2048] ----------------
__global__ void __launch_bounds__(256) softmax_kernel(float* __restrict__ out) {
    const int q = blockIdx.x;
    const int c = blockIdx.y;
    const int tid = threadIdx.x;
    __shared__ float red[8];

    float acc0 = 0.f, acc1 = 0.f, acc2 = 0.f, acc3 = 0.f;
    for (int n = 0; n < NB; n++) {
        const float* row = g_scores[c * 8 + n] + (size_t)q * LL;
        const float4 s = *(const float4*)&row[tid * 4];
        float m = fmaxf(fmaxf(s.x, s.y), fmaxf(s.z, s.w));
        m = blockReduceMax(m, red);
        const float e0 = __expf(s.x - m);
        const float e1 = __expf(s.y - m);
        const float e2 = __expf(s.z - m);
        const float e3 = __expf(s.w - m);
        float sum = e0 + e1 + e2 + e3;
        sum = blockReduceSum(sum, red);
        const float r = 1.0f / sum;
        acc0 += e0 * r; acc1 += e1 * r; acc2 += e2 * r; acc3 += e3 * r;
    }
    const int rowBase = (c >= 2) ? 1024 : 0;
    const int colBase = (c == 1 || c == 3) ? 1024 : 0;
    float4 o;
    o.x = acc0 * 0.125f; o.y = acc1 * 0.125f;
    o.z = acc2 * 0.125f; o.w = acc3 * 0.125f;
    *(float4*)&out[(size_t)(rowBase + q) * 2048 + colBase + tid * 4] = o;
}

// ---------------- launch ----------------
extern "C" void kernel_launch(void* const* d_in, const int* in_sizes, int n_in,
                              void* d_out, int out_size) {
    (void)in_sizes; (void)n_in; (void)out_size;
    const float* mA  = (const float*)d_in[0];
    const float* mB  = (const float*)d_in[1];
    const float* WqA = (const float*)d_in[2];
    const float* bqA = (const float*)d_in[3];
    const float* WkA = (const float*)d_in[4];
    const float* bkA = (const float*)d_in[5];
    const float* WqB = (const float*)d_in[6];
    const float* bqB = (const float*)d_in[7];
    const float* WkB = (const float*)d_in[8];
    const float* bkB = (const float*)d_in[9];
    float* out = (float*)d_out;

    static bool attr_done = false;
    if (!attr_done) {
        cudaFuncSetAttribute(proj_mma,  cudaFuncAttributeMaxDynamicSharedMemorySize, SMEM_SZ);
        cudaFuncSetAttribute(score_mma, cudaFuncAttributeMaxDynamicSharedMemorySize, SMEM_SZ);
        attr_done = true;
    }

    const float inv_scale = 1.0f / (4.0f * sqrtf(512.0f));

    // projections: M=8192 (64 tiles), N=512 (2 tiles of 256), 4 combos
    proj_mma<<<dim3(2, 64, 4), 256, SMEM_SZ>>>(mA, mB, WqA, bqA, WkA, bkA,
                                               WqB, bqB, WkB, bkB);

    // scores: 32 GEMMs of 1024x1024 -> 8 m-tiles x 4 n-tiles each
    score_mma<<<dim3(4, 8, 32), 256, SMEM_SZ>>>(inv_scale);

    // softmax + mean
    softmax_kernel<<<dim3(LL, 4), 256>>>(out);
}

// round 15
// speedup vs baseline: 1.0389x; 1.0389x over previous
#include <cuda_runtime.h>
#include <cmath>
#include <cstdint>

#define NB 8
#define LL 1024
#define EE 512

// ---------------- scratch (static __device__, no allocs) ----------------
// All staged operands are tf32-rounded and K-permuted (within each 8-group:
// col r -> 2r for r<4, 2(r-4)+1 for r>=4) so MMA fragments load as LDS.64.
__device__ float g_x[2][NB * LL * EE];   // modal A/B (rounded, k-permuted)
__device__ float g_w[4][EE * EE];        // weights   (rounded, k-permuted)
__device__ float g_p[4][NB * LL * EE];   // projections (rounded, col-permuted)
__device__ float g_scores[32][LL * LL];  // [combo*8+n][q][k]

// ---------------- PTX helpers ----------------
__device__ __forceinline__ uint32_t smem_u32(const void* p) {
    uint32_t a;
    asm("{ .reg .u64 t; cvta.to.shared.u64 t, %1; cvt.u32.u64 %0, t; }"
        : "=r"(a) : "l"(p));
    return a;
}
__device__ __forceinline__ uint32_t f2tf32(float x) {
    uint32_t u;
    asm("cvt.rna.tf32.f32 %0, %1;" : "=r"(u) : "f"(x));
    return u;
}
#define CP_ASYNC16(sa, gp) \
    asm volatile("cp.async.cg.shared.global [%0], [%1], 16;" :: "r"(sa), "l"(gp) : "memory")
#define CP_COMMIT() asm volatile("cp.async.commit_group;" ::: "memory")
#define CP_WAIT1()  asm volatile("cp.async.wait_group 1;" ::: "memory")
#define CP_WAIT0()  asm volatile("cp.async.wait_group 0;" ::: "memory")

__device__ __forceinline__ void mma_tf32(float* d, const uint32_t* a,
                                         const uint32_t* b) {
    asm volatile(
        "mma.sync.aligned.m16n8k8.row.col.f32.tf32.tf32.f32 "
        "{%0,%1,%2,%3}, {%4,%5,%6,%7}, {%8,%9}, {%0,%1,%2,%3};"
        : "+f"(d[0]), "+f"(d[1]), "+f"(d[2]), "+f"(d[3])
        : "r"(a[0]), "r"(a[1]), "r"(a[2]), "r"(a[3]), "r"(b[0]), "r"(b[1]));
}

// ---------------- GEMM core: D(128x256,f32) = A(128xK) * B(256xK)^T ------
// 256 threads, 8 warps (2m x 4n), warp tile 64x64 (4x8 m16n8k8).
// K=512, chunk 32, 3-stage cp.async pipeline, 1 syncthreads/chunk.
// Operands are K-permuted so fragment loads are conflict-free LDS.64.
#define PITCH 40
#define KC 32
#define AROWS 128
#define BROWS 256
#define FA (AROWS * PITCH)
#define FBUF ((AROWS + BROWS) * PITCH)      // 15360 floats per stage
#define NSTAGE 3
#define SMEM_SZ (NSTAGE * FBUF * 4)         // 184320 bytes

__device__ __forceinline__ void load_chunk(const float* __restrict__ pa,
                                           const float* __restrict__ pb,
                                           int k0, uint32_t sa, uint32_t sb,
                                           int m0, int n0, int tid) {
#pragma unroll
    for (int i = 0; i < 4; i++) {
        const int u = tid + i * 256;
        const int row = u >> 3, seg = u & 7;
        CP_ASYNC16(sa + (uint32_t)(row * PITCH + seg * 4) * 4u,
                   pa + (size_t)(m0 + row) * EE + k0 + seg * 4);
    }
#pragma unroll
    for (int i = 0; i < 8; i++) {
        const int u = tid + i * 256;
        const int row = u >> 3, seg = u & 7;
        CP_ASYNC16(sb + (uint32_t)(row * PITCH + seg * 4) * 4u,
                   pb + (size_t)(n0 + row) * EE + k0 + seg * 4);
    }
    CP_COMMIT();
}

__device__ __forceinline__ void gemm_core(const float* __restrict__ A,
                                          const float* __restrict__ B,
                                          int m0, int n0,
                                          float acc[4][8][4]) {
    extern __shared__ float smem[];
    uint32_t sAu[NSTAGE], sBu[NSTAGE];
    const float* sAp[NSTAGE];
    const float* sBp[NSTAGE];
#pragma unroll
    for (int s = 0; s < NSTAGE; s++) {
        sAp[s] = smem + s * FBUF;
        sBp[s] = smem + s * FBUF + FA;
        sAu[s] = smem_u32(sAp[s]);
        sBu[s] = smem_u32(sBp[s]);
    }

    const int tid = threadIdx.x;
    const int lane = tid & 31;
    const int wid = tid >> 5;
    const int wm = (wid & 1) * 64;   // warp m offset
    const int wn = (wid >> 1) * 64;  // warp n offset
    const int g = lane >> 2;         // 0..7
    const int c = lane & 3;          // 0..3

#pragma unroll
    for (int mt = 0; mt < 4; mt++)
#pragma unroll
        for (int nt = 0; nt < 8; nt++)
#pragma unroll
            for (int j = 0; j < 4; j++) acc[mt][nt][j] = 0.f;

    load_chunk(A, B, 0,  sAu[0], sBu[0], m0, n0, tid);
    load_chunk(A, B, KC, sAu[1], sBu[1], m0, n0, tid);

    const int NCH = EE / KC;  // 16
    int bc = 0;               // buffer of current chunk
    for (int ch = 0; ch < NCH; ch++) {
        if (ch < NCH - 1) { CP_WAIT1(); } else { CP_WAIT0(); }
        __syncthreads();
        if (ch + 2 < NCH) {
            int bn = bc + 2; if (bn >= NSTAGE) bn -= NSTAGE;
            load_chunk(A, B, (ch + 2) * KC, sAu[bn], sBu[bn], m0, n0, tid);
        }

        const float* sA = sAp[bc];
        const float* sB = sBp[bc];
#pragma unroll
        for (int ks = 0; ks < KC / 8; ks++) {
            const int koff = ks * 8 + 2 * c;
            uint32_t af[4][4];
#pragma unroll
            for (int mt = 0; mt < 4; mt++) {
                const float* p = sA + (size_t)(wm + mt * 16 + g) * PITCH + koff;
                const float2 v0 = *(const float2*)p;               // cols c, c+4
                const float2 v1 = *(const float2*)(p + 8 * PITCH); // row+8
                af[mt][0] = __float_as_uint(v0.x);
                af[mt][1] = __float_as_uint(v1.x);
                af[mt][2] = __float_as_uint(v0.y);
                af[mt][3] = __float_as_uint(v1.y);
            }
            uint32_t bf[8][2];
#pragma unroll
            for (int nt = 0; nt < 8; nt++) {
                const float2 v = *(const float2*)(sB +
                    (size_t)(wn + nt * 8 + g) * PITCH + koff);
                bf[nt][0] = __float_as_uint(v.x);
                bf[nt][1] = __float_as_uint(v.y);
            }
#pragma unroll
            for (int mt = 0; mt < 4; mt++)
#pragma unroll
                for (int nt = 0; nt < 8; nt++)
                    mma_tf32(acc[mt][nt], af[mt], bf[nt]);
        }
        bc++; if (bc == NSTAGE) bc = 0;
    }
}

// ------------- convert: fp32 -> tf32(RNA), K-permuted within 8-groups -----
__global__ void __launch_bounds__(256) convert_kernel(
    const float* __restrict__ src, int kind, int idx, int n8) {
    int i = blockIdx.x * blockDim.x + threadIdx.x;
    if (i >= n8) return;
    float* dst = kind ? g_w[idx] : g_x[idx];
    const float4 v0 = ((const float4*)src)[2 * i];
    const float4 v1 = ((const float4*)src)[2 * i + 1];
    uint4 o0, o1;
    o0.x = f2tf32(v0.x); o0.y = f2tf32(v1.x);
    o0.z = f2tf32(v0.y); o0.w = f2tf32(v1.y);
    o1.x = f2tf32(v0.z); o1.y = f2tf32(v1.z);
    o1.z = f2tf32(v0.w); o1.w = f2tf32(v1.w);
    ((uint4*)dst)[2 * i]     = o0;
    ((uint4*)dst)[2 * i + 1] = o1;
}

__device__ __forceinline__ int permcol(int x) {
    const int r = x & 7, base = x & ~7;
    return base + ((r < 4) ? 2 * r : 2 * (r - 4) + 1);
}

// ---------------- projections: q/k = x @ W^T + b ----------------
__global__ void __launch_bounds__(256) proj_mma(
    const float* __restrict__ bqA, const float* __restrict__ bkA,
    const float* __restrict__ bqB, const float* __restrict__ bkB) {
    const int cc = blockIdx.z;
    const int m0 = blockIdx.y * 128, n0 = blockIdx.x * 256;
    const float* bias = (cc == 0) ? bqA : (cc == 1) ? bkA : (cc == 2) ? bqB : bkB;

    float acc[4][8][4];
    gemm_core(g_x[cc >> 1], g_w[cc], m0, n0, acc);

    const int lane = threadIdx.x & 31, wid = threadIdx.x >> 5;
    const int wm = (wid & 1) * 64, wn = (wid >> 1) * 64;
    const int g = lane >> 2, c2 = (lane & 3) * 2;
    float* out = g_p[cc];
#pragma unroll
    for (int nt = 0; nt < 8; nt++) {
        const int n = n0 + wn + nt * 8 + c2;
        const float bv0 = __ldg(&bias[n]);
        const float bv1 = __ldg(&bias[n + 1]);
        const int p0 = permcol(n);       // output cols stored K-permuted
        const int p1 = permcol(n + 1);   // so score GEMM loads LDS.64 too
#pragma unroll
        for (int mt = 0; mt < 4; mt++) {
#pragma unroll
            for (int h = 0; h < 2; h++) {
                const int m = m0 + wm + mt * 16 + h * 8 + g;
                float* row = out + (size_t)m * EE;
                ((uint32_t*)row)[p0] = f2tf32(acc[mt][nt][2 * h] + bv0);
                ((uint32_t*)row)[p1] = f2tf32(acc[mt][nt][2 * h + 1] + bv1);
            }
        }
    }
}

// ---------------- scores: S = q @ k^T * inv_scale ----------------
__global__ void __launch_bounds__(256) score_mma(float scale) {
    const int z = blockIdx.z, cc = z >> 3, nn = z & 7;
    const int qsel = (cc < 2) ? 0 : 2;
    const int ksel = (cc == 0 || cc == 3) ? 1 : 3;
    const size_t off = (size_t)nn * LL * EE;
    const int m0 = blockIdx.y * 128, n0 = blockIdx.x * 256;

    float acc[4][8][4];
    gemm_core(g_p[qsel] + off, g_p[ksel] + off, m0, n0, acc);

    const int lane = threadIdx.x & 31, wid = threadIdx.x >> 5;
    const int wm = (wid & 1) * 64, wn = (wid >> 1) * 64;
    const int g = lane >> 2, c2 = (lane & 3) * 2;
    float* out = g_scores[z];
#pragma unroll
    for (int mt = 0; mt < 4; mt++) {
#pragma unroll
        for (int h = 0; h < 2; h++) {
            const int m = m0 + wm + mt * 16 + h * 8 + g;
            float* row = out + (size_t)m * LL;
#pragma unroll
            for (int nt = 0; nt < 8; nt++) {
                float2 v;
                v.x = acc[mt][nt][2 * h] * scale;
                v.y = acc[mt][nt][2 * h + 1] * scale;
                *(float2*)&row[n0 + wn + nt * 8 + c2] = v;
            }
        }
    }
}

// ---------------- block reductions ----------------
__device__ __forceinline__ float blockReduceMax(float v, float* red) {
#pragma unroll
    for (int o = 16; o > 0; o >>= 1) v = fmaxf(v, __shfl_xor_sync(0xffffffffu, v, o));
    const int w = threadIdx.x >> 5;
    if ((threadIdx.x & 31) == 0) red[w] = v;
    __syncthreads();
    if (threadIdx.x < 8) {
        float t = red[threadIdx.x];
#pragma unroll
        for (int o = 4; o > 0; o >>= 1) t = fmaxf(t, __shfl_xor_sync(0xffu, t, o));
        if (threadIdx.x == 0) red[0] = t;
    }
    __syncthreads();
    v = red[0];
    __syncthreads();
    return v;
}
__device__ __forceinline__ float blockReduceSum(float v, float* red) {
#pragma unroll
    for (int o = 16; o > 0; o >>= 1) v += __shfl_xor_sync(0xffffffffu, v, o);
    const int w = threadIdx.x >> 5;
    if ((threadIdx.x & 31) == 0) red[w] = v;
    __syncthreads();
    if (threadIdx.x < 8) {
        float t = red[threadIdx.x];
#pragma unroll
        for (int o = 4; o > 0; o >>= 1) t += __shfl_xor_sync(0xffu, t, o);
        if (threadIdx.x == 0) red[0] = t;
    }
    __syncthreads();
    v = red[0];
    __syncthreads();
    return v;
}

// ---------------- softmax + mean over N, write [2048,2048] ----------------
__global__ void __launch_bounds__(256) softmax_kernel(float* __restrict__ out) {
    const int q = blockIdx.x;
    const int c = blockIdx.y;
    const int tid = threadIdx.x;
    __shared__ float red[8];

    float acc0 = 0.f, acc1 = 0.f, acc2 = 0.f, acc3 = 0.f;
    for (int n = 0; n < NB; n++) {
        const float* row = g_scores[c * 8 + n] + (size_t)q * LL;
        const float4 s = *(const float4*)&row[tid * 4];
        float m = fmaxf(fmaxf(s.x, s.y), fmaxf(s.z, s.w));
        m = blockReduceMax(m, red);
        const float e0 = __expf(s.x - m);
        const float e1 = __expf(s.y - m);
        const float e2 = __expf(s.z - m);
        const float e3 = __expf(s.w - m);
        float sum = e0 + e1 + e2 + e3;
        sum = blockReduceSum(sum, red);
        const float r = 1.0f / sum;
        acc0 += e0 * r; acc1 += e1 * r; acc2 += e2 * r; acc3 += e3 * r;
    }
    const int rowBase = (c >= 2) ? 1024 : 0;
    const int colBase = (c == 1 || c == 3) ? 1024 : 0;
    float4 o;
    o.x = acc0 * 0.125f; o.y = acc1 * 0.125f;
    o.z = acc2 * 0.125f; o.w = acc3 * 0.125f;
    *(float4*)&out[(size_t)(rowBase + q) * 2048 + colBase + tid * 4] = o;
}

// ---------------- launch ----------------
extern "C" void kernel_launch(void* const* d_in, const int* in_sizes, int n_in,
                              void* d_out, int out_size) {
    (void)in_sizes; (void)n_in; (void)out_size;
    const float* mA  = (const float*)d_in[0];
    const float* mB  = (const float*)d_in[1];
    const float* WqA = (const float*)d_in[2];
    const float* bqA = (const float*)d_in[3];
    const float* WkA = (const float*)d_in[4];
    const float* bkA = (const float*)d_in[5];
    const float* WqB = (const float*)d_in[6];
    const float* bqB = (const float*)d_in[7];
    const float* WkB = (const float*)d_in[8];
    const float* bkB = (const float*)d_in[9];
    float* out = (float*)d_out;

    static bool attr_done = false;
    if (!attr_done) {
        cudaFuncSetAttribute(proj_mma,  cudaFuncAttributeMaxDynamicSharedMemorySize, SMEM_SZ);
        cudaFuncSetAttribute(score_mma, cudaFuncAttributeMaxDynamicSharedMemorySize, SMEM_SZ);
        attr_done = true;
    }

    const float inv_scale = 1.0f / (4.0f * sqrtf(512.0f));

    const int n8x = NB * LL * EE / 8;   // 524288
    const int n8w = EE * EE / 8;        // 32768
    convert_kernel<<<(n8x + 255) / 256, 256>>>(mA,  0, 0, n8x);
    convert_kernel<<<(n8x + 255) / 256, 256>>>(mB,  0, 1, n8x);
    convert_kernel<<<(n8w + 255) / 256, 256>>>(WqA, 1, 0, n8w);
    convert_kernel<<<(n8w + 255) / 256, 256>>>(WkA, 1, 1, n8w);
    convert_kernel<<<(n8w + 255) / 256, 256>>>(WqB, 1, 2, n8w);
    convert_kernel<<<(n8w + 255) / 256, 256>>>(WkB, 1, 3, n8w);

    // projections: M=8192 (64 tiles), N=512 (2 tiles of 256), 4 combos
    proj_mma<<<dim3(2, 64, 4), 256, SMEM_SZ>>>(bqA, bkA, bqB, bkB);

    // scores: 32 GEMMs of 1024x1024 -> 8 m-tiles x 4 n-tiles each
    score_mma<<<dim3(4, 8, 32), 256, SMEM_SZ>>>(inv_scale);

    // softmax + mean
    softmax_kernel<<<dim3(LL, 4), 256>>>(out);
}

// round 16
// speedup vs baseline: 1.0586x; 1.0189x over previous
#include <cuda_runtime.h>
#include <cmath>
#include <cstdint>

#define NB 8
#define LL 1024
#define EE 512

// ---------------- scratch (static __device__, no allocs) ----------------
// All staged operands are tf32-rounded and K-permuted (within each 8-group:
// col r -> 2r for r<4, 2(r-4)+1 for r>=4) so MMA fragments load as LDS.64.
__device__ float g_x[2][NB * LL * EE];   // modal A/B (rounded, k-permuted)
__device__ float g_w[4][EE * EE];        // weights   (rounded, k-permuted)
__device__ float g_p[4][NB * LL * EE];   // projections (rounded, col-permuted)
__device__ float g_scores[32][LL * LL];  // [combo*8+n][q][k]

// ---------------- PTX helpers ----------------
__device__ __forceinline__ uint32_t smem_u32(const void* p) {
    uint32_t a;
    asm("{ .reg .u64 t; cvta.to.shared.u64 t, %1; cvt.u32.u64 %0, t; }"
        : "=r"(a) : "l"(p));
    return a;
}
__device__ __forceinline__ uint32_t f2tf32(float x) {
    uint32_t u;
    asm("cvt.rna.tf32.f32 %0, %1;" : "=r"(u) : "f"(x));
    return u;
}
#define CP_ASYNC16(sa, gp) \
    asm volatile("cp.async.cg.shared.global [%0], [%1], 16;" :: "r"(sa), "l"(gp) : "memory")
#define CP_COMMIT() asm volatile("cp.async.commit_group;" ::: "memory")
#define CP_WAIT1()  asm volatile("cp.async.wait_group 1;" ::: "memory")
#define CP_WAIT0()  asm volatile("cp.async.wait_group 0;" ::: "memory")

__device__ __forceinline__ void mma_tf32(float* d, const uint32_t* a,
                                         const uint32_t* b) {
    asm volatile(
        "mma.sync.aligned.m16n8k8.row.col.f32.tf32.tf32.f32 "
        "{%0,%1,%2,%3}, {%4,%5,%6,%7}, {%8,%9}, {%0,%1,%2,%3};"
        : "+f"(d[0]), "+f"(d[1]), "+f"(d[2]), "+f"(d[3])
        : "r"(a[0]), "r"(a[1]), "r"(a[2]), "r"(a[3]), "r"(b[0]), "r"(b[1]));
}

// ---------------- GEMM core: D(128x128,f32) = A(128xK) * B(128xK)^T ------
// 256 threads, 8 warps (2m x 4n), warp tile 64x32 (4x4 m16n8k8), acc 64 regs.
// K=512, chunk 32, 2-stage cp.async double buffer, 2 CTAs/SM for latency hiding.
#define PITCH 40
#define KC 32
#define TROWS 128
#define FA (TROWS * PITCH)
#define FBUF (2 * TROWS * PITCH)            // 10240 floats per stage
#define SMEM_SZ (2 * FBUF * 4)              // 81920 bytes

__device__ __forceinline__ void load_chunk(const float* __restrict__ pa,
                                           const float* __restrict__ pb,
                                           int k0, uint32_t sa, uint32_t sb,
                                           int m0, int n0, int tid) {
#pragma unroll
    for (int i = 0; i < 4; i++) {
        const int u = tid + i * 256;
        const int row = u >> 3, seg = u & 7;
        const uint32_t so = (uint32_t)(row * PITCH + seg * 4) * 4u;
        CP_ASYNC16(sa + so, pa + (size_t)(m0 + row) * EE + k0 + seg * 4);
        CP_ASYNC16(sb + so, pb + (size_t)(n0 + row) * EE + k0 + seg * 4);
    }
    CP_COMMIT();
}

__device__ __forceinline__ void gemm_core(const float* __restrict__ A,
                                          const float* __restrict__ B,
                                          int m0, int n0,
                                          float acc[4][4][4]) {
    extern __shared__ float smem[];
    const float* sAp[2] = {smem, smem + FBUF};
    const float* sBp[2] = {smem + FA, smem + FBUF + FA};
    const uint32_t sAu[2] = {smem_u32(sAp[0]), smem_u32(sAp[1])};
    const uint32_t sBu[2] = {smem_u32(sBp[0]), smem_u32(sBp[1])};

    const int tid = threadIdx.x;
    const int lane = tid & 31;
    const int wid = tid >> 5;
    const int wm = (wid & 1) * 64;   // warp m offset
    const int wn = (wid >> 1) * 32;  // warp n offset
    const int g = lane >> 2;         // 0..7
    const int c = lane & 3;          // 0..3

#pragma unroll
    for (int mt = 0; mt < 4; mt++)
#pragma unroll
        for (int nt = 0; nt < 4; nt++)
#pragma unroll
            for (int j = 0; j < 4; j++) acc[mt][nt][j] = 0.f;

    load_chunk(A, B, 0, sAu[0], sBu[0], m0, n0, tid);

    const int NCH = EE / KC;  // 16
    for (int ch = 0; ch < NCH; ch++) {
        const int buf = ch & 1;
        if (ch + 1 < NCH)
            load_chunk(A, B, (ch + 1) * KC, sAu[buf ^ 1], sBu[buf ^ 1], m0, n0, tid);
        if (ch + 1 < NCH) { CP_WAIT1(); } else { CP_WAIT0(); }
        __syncthreads();

        const float* sA = sAp[buf];
        const float* sB = sBp[buf];
#pragma unroll
        for (int ks = 0; ks < KC / 8; ks++) {
            const int koff = ks * 8 + 2 * c;
            uint32_t af[4][4];
#pragma unroll
            for (int mt = 0; mt < 4; mt++) {
                const float* p = sA + (size_t)(wm + mt * 16 + g) * PITCH + koff;
                const float2 v0 = *(const float2*)p;               // cols c, c+4
                const float2 v1 = *(const float2*)(p + 8 * PITCH); // row+8
                af[mt][0] = __float_as_uint(v0.x);
                af[mt][1] = __float_as_uint(v1.x);
                af[mt][2] = __float_as_uint(v0.y);
                af[mt][3] = __float_as_uint(v1.y);
            }
            uint32_t bf[4][2];
#pragma unroll
            for (int nt = 0; nt < 4; nt++) {
                const float2 v = *(const float2*)(sB +
                    (size_t)(wn + nt * 8 + g) * PITCH + koff);
                bf[nt][0] = __float_as_uint(v.x);
                bf[nt][1] = __float_as_uint(v.y);
            }
#pragma unroll
            for (int mt = 0; mt < 4; mt++)
#pragma unroll
                for (int nt = 0; nt < 4; nt++)
                    mma_tf32(acc[mt][nt], af[mt], bf[nt]);
        }
        __syncthreads();
    }
}

// ------------- convert: fp32 -> tf32(RNA), K-permuted within 8-groups -----
__global__ void __launch_bounds__(256) convert_kernel(
    const float* __restrict__ src, int kind, int idx, int n8) {
    int i = blockIdx.x * blockDim.x + threadIdx.x;
    if (i >= n8) return;
    float* dst = kind ? g_w[idx] : g_x[idx];
    const float4 v0 = ((const float4*)src)[2 * i];
    const float4 v1 = ((const float4*)src)[2 * i + 1];
    uint4 o0, o1;
    o0.x = f2tf32(v0.x); o0.y = f2tf32(v1.x);
    o0.z = f2tf32(v0.y); o0.w = f2tf32(v1.y);
    o1.x = f2tf32(v0.z); o1.y = f2tf32(v1.z);
    o1.z = f2tf32(v0.w); o1.w = f2tf32(v1.w);
    ((uint4*)dst)[2 * i]     = o0;
    ((uint4*)dst)[2 * i + 1] = o1;
}

__device__ __forceinline__ int permcol(int x) {
    const int r = x & 7, base = x & ~7;
    return base + ((r < 4) ? 2 * r : 2 * (r - 4) + 1);
}

// ---------------- projections: q/k = x @ W^T + b ----------------
__global__ void __launch_bounds__(256, 2) proj_mma(
    const float* __restrict__ bqA, const float* __restrict__ bkA,
    const float* __restrict__ bqB, const float* __restrict__ bkB) {
    const int cc = blockIdx.z;
    const int m0 = blockIdx.y * 128, n0 = blockIdx.x * 128;
    const float* bias = (cc == 0) ? bqA : (cc == 1) ? bkA : (cc == 2) ? bqB : bkB;

    float acc[4][4][4];
    gemm_core(g_x[cc >> 1], g_w[cc], m0, n0, acc);

    const int lane = threadIdx.x & 31, wid = threadIdx.x >> 5;
    const int wm = (wid & 1) * 64, wn = (wid >> 1) * 32;
    const int g = lane >> 2, c2 = (lane & 3) * 2;
    float* out = g_p[cc];
#pragma unroll
    for (int nt = 0; nt < 4; nt++) {
        const int n = n0 + wn + nt * 8 + c2;
        const float bv0 = __ldg(&bias[n]);
        const float bv1 = __ldg(&bias[n + 1]);
        const int p0 = permcol(n);       // output cols stored K-permuted
        const int p1 = permcol(n + 1);   // so score GEMM loads LDS.64 too
#pragma unroll
        for (int mt = 0; mt < 4; mt++) {
#pragma unroll
            for (int h = 0; h < 2; h++) {
                const int m = m0 + wm + mt * 16 + h * 8 + g;
                float* row = out + (size_t)m * EE;
                ((uint32_t*)row)[p0] = f2tf32(acc[mt][nt][2 * h] + bv0);
                ((uint32_t*)row)[p1] = f2tf32(acc[mt][nt][2 * h + 1] + bv1);
            }
        }
    }
}

// ---------------- scores: S = q @ k^T * inv_scale ----------------
__global__ void __launch_bounds__(256, 2) score_mma(float scale) {
    const int z = blockIdx.z, cc = z >> 3, nn = z & 7;
    const int qsel = (cc < 2) ? 0 : 2;
    const int ksel = (cc == 0 || cc == 3) ? 1 : 3;
    const size_t off = (size_t)nn * LL * EE;
    const int m0 = blockIdx.y * 128, n0 = blockIdx.x * 128;

    float acc[4][4][4];
    gemm_core(g_p[qsel] + off, g_p[ksel] + off, m0, n0, acc);

    const int lane = threadIdx.x & 31, wid = threadIdx.x >> 5;
    const int wm = (wid & 1) * 64, wn = (wid >> 1) * 32;
    const int g = lane >> 2, c2 = (lane & 3) * 2;
    float* out = g_scores[z];
#pragma unroll
    for (int mt = 0; mt < 4; mt++) {
#pragma unroll
        for (int h = 0; h < 2; h++) {
            const int m = m0 + wm + mt * 16 + h * 8 + g;
            float* row = out + (size_t)m * LL;
#pragma unroll
            for (int nt = 0; nt < 4; nt++) {
                float2 v;
                v.x = acc[mt][nt][2 * h] * scale;
                v.y = acc[mt][nt][2 * h + 1] * scale;
                *(float2*)&row[n0 + wn + nt * 8 + c2] = v;
            }
        }
    }
}

// ---------------- block reductions ----------------
__device__ __forceinline__ float blockReduceMax(float v, float* red) {
#pragma unroll
    for (int o = 16; o > 0; o >>= 1) v = fmaxf(v, __shfl_xor_sync(0xffffffffu, v, o));
    const int w = threadIdx.x >> 5;
    if ((threadIdx.x & 31) == 0) red[w] = v;
    __syncthreads();
    if (threadIdx.x < 8) {
        float t = red[threadIdx.x];
#pragma unroll
        for (int o = 4; o > 0; o >>= 1) t = fmaxf(t, __shfl_xor_sync(0xffu, t, o));
        if (threadIdx.x == 0) red[0] = t;
    }
    __syncthreads();
    v = red[0];
    __syncthreads();
    return v;
}
__device__ __forceinline__ float blockReduceSum(float v, float* red) {
#pragma unroll
    for (int o = 16; o > 0; o >>= 1) v += __shfl_xor_sync(0xffffffffu, v, o);
    const int w = threadIdx.x >> 5;
    if ((threadIdx.x & 31) == 0) red[w] = v;
    __syncthreads();
    if (threadIdx.x < 8) {
        float t = red[threadIdx.x];
#pragma unroll
        for (int o = 4; o > 0; o >>= 1) t += __shfl_xor_sync(0xffu, t, o);
        if (threadIdx.x == 0) red[0] = t;
    }
    __syncthreads();
    v = red[0];
    __syncthreads();
    return v;
}

// ---------------- softmax + mean over N, write [2048,2048] ----------------
__global__ void __launch_bounds__(256) softmax_kernel(float* __restrict__ out) {
    const int q = blockIdx.x;
    const int c = blockIdx.y;
    const int tid = threadIdx.x;
    __shared__ float red[8];

    float acc0 = 0.f, acc1 = 0.f, acc2 = 0.f, acc3 = 0.f;
    for (int n = 0; n < NB; n++) {
        const float* row = g_scores[c * 8 + n] + (size_t)q * LL;
        const float4 s = *(const float4*)&row[tid * 4];
        float m = fmaxf(fmaxf(s.x, s.y), fmaxf(s.z, s.w));
        m = blockReduceMax(m, red);
        const float e0 = __expf(s.x - m);
        const float e1 = __expf(s.y - m);
        const float e2 = __expf(s.z - m);
        const float e3 = __expf(s.w - m);
        float sum = e0 + e1 + e2 + e3;
        sum = blockReduceSum(sum, red);
        const float r = 1.0f / sum;
        acc0 += e0 * r; acc1 += e1 * r; acc2 += e2 * r; acc3 += e3 * r;
    }
    const int rowBase = (c >= 2) ? 1024 : 0;
    const int colBase = (c == 1 || c == 3) ? 1024 : 0;
    float4 o;
    o.x = acc0 * 0.125f; o.y = acc1 * 0.125f;
    o.z = acc2 * 0.125f; o.w = acc3 * 0.125f;
    *(float4*)&out[(size_t)(rowBase + q) * 2048 + colBase + tid * 4] = o;
}

// ---------------- launch ----------------
extern "C" void kernel_launch(void* const* d_in, const int* in_sizes, int n_in,
                              void* d_out, int out_size) {
    (void)in_sizes; (void)n_in; (void)out_size;
    const float* mA  = (const float*)d_in[0];
    const float* mB  = (const float*)d_in[1];
    const float* WqA = (const float*)d_in[2];
    const float* bqA = (const float*)d_in[3];
    const float* WkA = (const float*)d_in[4];
    const float* bkA = (const float*)d_in[5];
    const float* WqB = (const float*)d_in[6];
    const float* bqB = (const float*)d_in[7];
    const float* WkB = (const float*)d_in[8];
    const float* bkB = (const float*)d_in[9];
    float* out = (float*)d_out;

    static bool attr_done = false;
    if (!attr_done) {
        cudaFuncSetAttribute(proj_mma,  cudaFuncAttributeMaxDynamicSharedMemorySize, SMEM_SZ);
        cudaFuncSetAttribute(score_mma, cudaFuncAttributeMaxDynamicSharedMemorySize, SMEM_SZ);
        attr_done = true;
    }

    const float inv_scale = 1.0f / (4.0f * sqrtf(512.0f));

    const int n8x = NB * LL * EE / 8;   // 524288
    const int n8w = EE * EE / 8;        // 32768
    convert_kernel<<<(n8x + 255) / 256, 256>>>(mA,  0, 0, n8x);
    convert_kernel<<<(n8x + 255) / 256, 256>>>(mB,  0, 1, n8x);
    convert_kernel<<<(n8w + 255) / 256, 256>>>(WqA, 1, 0, n8w);
    convert_kernel<<<(n8w + 255) / 256, 256>>>(WkA, 1, 1, n8w);
    convert_kernel<<<(n8w + 255) / 256, 256>>>(WqB, 1, 2, n8w);
    convert_kernel<<<(n8w + 255) / 256, 256>>>(WkB, 1, 3, n8w);

    // projections: M=8192 (64 tiles), N=512 (4 tiles), 4 combos
    proj_mma<<<dim3(4, 64, 4), 256, SMEM_SZ>>>(bqA, bkA, bqB, bkB);

    // scores: 32 GEMMs of 1024x1024 -> 8x8 tiles each
    score_mma<<<dim3(8, 8, 32), 256, SMEM_SZ>>>(inv_scale);

    // softmax + mean
    softmax_kernel<<<dim3(LL, 4), 256>>>(out);
}

// round 17
// speedup vs baseline: 1.0793x; 1.0195x over previous
#include <cuda_runtime.h>
#include <cmath>
#include <cstdint>

#define NB 8
#define LL 1024
#define EE 512

// ---------------- scratch (static __device__, no allocs) ----------------
// All staged operands are tf32-rounded and K-permuted (within each 8-group:
// col r -> 2r for r<4, 2(r-4)+1 for r>=4) so MMA fragments load as LDS.64.
__device__ float g_x[2][NB * LL * EE];   // modal A/B (rounded, k-permuted)
__device__ float g_w[4][EE * EE];        // weights   (rounded, k-permuted)
__device__ float g_p[4][NB * LL * EE];   // projections (rounded, col-permuted)
__device__ float g_scores[32][LL * LL];  // [combo*8+n][q][k]

// ---------------- PTX helpers ----------------
__device__ __forceinline__ uint32_t smem_u32(const void* p) {
    uint32_t a;
    asm("{ .reg .u64 t; cvta.to.shared.u64 t, %1; cvt.u32.u64 %0, t; }"
        : "=r"(a) : "l"(p));
    return a;
}
__device__ __forceinline__ uint32_t f2tf32(float x) {
    uint32_t u;
    asm("cvt.rna.tf32.f32 %0, %1;" : "=r"(u) : "f"(x));
    return u;
}
#define CP_ASYNC16(sa, gp) \
    asm volatile("cp.async.cg.shared.global [%0], [%1], 16;" :: "r"(sa), "l"(gp) : "memory")
#define CP_COMMIT() asm volatile("cp.async.commit_group;" ::: "memory")
#define CP_WAIT0()  asm volatile("cp.async.wait_group 0;" ::: "memory")

__device__ __forceinline__ void mma_tf32(float* d, const uint32_t* a,
                                         const uint32_t* b) {
    asm volatile(
        "mma.sync.aligned.m16n8k8.row.col.f32.tf32.tf32.f32 "
        "{%0,%1,%2,%3}, {%4,%5,%6,%7}, {%8,%9}, {%0,%1,%2,%3};"
        : "+f"(d[0]), "+f"(d[1]), "+f"(d[2]), "+f"(d[3])
        : "r"(a[0]), "r"(a[1]), "r"(a[2]), "r"(a[3]), "r"(b[0]), "r"(b[1]));
}

// ---------------- GEMM core: D(128x128,f32) = A(128xK) * B(128xK)^T ------
// 256 threads, 8 warps (2m x 4n), warp tile 64x32 (4x4 m16n8k8), acc 64 regs.
// K=512, chunk 32, 2-stage cp.async, ONE syncthreads per chunk, fragment
// double-buffering across k-steps. 2 CTAs/SM.
#define PITCH 40
#define KC 32
#define TROWS 128
#define FA (TROWS * PITCH)
#define FBUF (2 * TROWS * PITCH)            // 10240 floats per stage
#define SMEM_SZ (2 * FBUF * 4)              // 81920 bytes

__device__ __forceinline__ void load_chunk(const float* __restrict__ pa,
                                           const float* __restrict__ pb,
                                           int k0, uint32_t sa, uint32_t sb,
                                           int m0, int n0, int tid) {
#pragma unroll
    for (int i = 0; i < 4; i++) {
        const int u = tid + i * 256;
        const int row = u >> 3, seg = u & 7;
        const uint32_t so = (uint32_t)(row * PITCH + seg * 4) * 4u;
        CP_ASYNC16(sa + so, pa + (size_t)(m0 + row) * EE + k0 + seg * 4);
        CP_ASYNC16(sb + so, pb + (size_t)(n0 + row) * EE + k0 + seg * 4);
    }
    CP_COMMIT();
}

__device__ __forceinline__ void frag_load(uint32_t af[4][4], uint32_t bf[4][2],
                                          const float* sA, const float* sB,
                                          int wm, int wn, int g, int koff) {
#pragma unroll
    for (int mt = 0; mt < 4; mt++) {
        const float* p = sA + (size_t)(wm + mt * 16 + g) * PITCH + koff;
        const float2 v0 = *(const float2*)p;               // cols c, c+4
        const float2 v1 = *(const float2*)(p + 8 * PITCH); // row+8
        af[mt][0] = __float_as_uint(v0.x);
        af[mt][1] = __float_as_uint(v1.x);
        af[mt][2] = __float_as_uint(v0.y);
        af[mt][3] = __float_as_uint(v1.y);
    }
#pragma unroll
    for (int nt = 0; nt < 4; nt++) {
        const float2 v = *(const float2*)(sB +
            (size_t)(wn + nt * 8 + g) * PITCH + koff);
        bf[nt][0] = __float_as_uint(v.x);
        bf[nt][1] = __float_as_uint(v.y);
    }
}

__device__ __forceinline__ void gemm_core(const float* __restrict__ A,
                                          const float* __restrict__ B,
                                          int m0, int n0,
                                          float acc[4][4][4]) {
    extern __shared__ float smem[];
    const float* sAp[2] = {smem, smem + FBUF};
    const float* sBp[2] = {smem + FA, smem + FBUF + FA};
    const uint32_t sAu[2] = {smem_u32(sAp[0]), smem_u32(sAp[1])};
    const uint32_t sBu[2] = {smem_u32(sBp[0]), smem_u32(sBp[1])};

    const int tid = threadIdx.x;
    const int lane = tid & 31;
    const int wid = tid >> 5;
    const int wm = (wid & 1) * 64;   // warp m offset
    const int wn = (wid >> 1) * 32;  // warp n offset
    const int g = lane >> 2;         // 0..7
    const int c = lane & 3;          // 0..3

#pragma unroll
    for (int mt = 0; mt < 4; mt++)
#pragma unroll
        for (int nt = 0; nt < 4; nt++)
#pragma unroll
            for (int j = 0; j < 4; j++) acc[mt][nt][j] = 0.f;

    load_chunk(A, B, 0, sAu[0], sBu[0], m0, n0, tid);

    uint32_t af[2][4][4];
    uint32_t bf[2][4][2];

    const int NCH = EE / KC;  // 16
    for (int ch = 0; ch < NCH; ch++) {
        const int buf = ch & 1;
        CP_WAIT0();
        __syncthreads();
        // Safe: after the sync, buf^1's previous contents (chunk ch-1) are
        // fully consumed by all threads; overwrite it with chunk ch+1.
        if (ch + 1 < NCH)
            load_chunk(A, B, (ch + 1) * KC, sAu[buf ^ 1], sBu[buf ^ 1], m0, n0, tid);

        const float* sA = sAp[buf];
        const float* sB = sBp[buf];
        frag_load(af[0], bf[0], sA, sB, wm, wn, g, 2 * c);
#pragma unroll
        for (int ks = 0; ks < KC / 8; ks++) {
            const int cur = ks & 1;
            if (ks + 1 < KC / 8)
                frag_load(af[cur ^ 1], bf[cur ^ 1], sA, sB, wm, wn, g,
                          (ks + 1) * 8 + 2 * c);
#pragma unroll
            for (int mt = 0; mt < 4; mt++)
#pragma unroll
                for (int nt = 0; nt < 4; nt++)
                    mma_tf32(acc[mt][nt], af[cur][mt], bf[cur][nt]);
        }
    }
}

// ------- fused convert: fp32 -> tf32(RNA), K-permuted, all 6 tensors -------
#define N8X (NB * LL * EE / 8)   // 524288 per modal
#define N8W (EE * EE / 8)        // 32768 per weight
__global__ void __launch_bounds__(256) convert_all(
    const float* __restrict__ mA, const float* __restrict__ mB,
    const float* __restrict__ WqA, const float* __restrict__ WkA,
    const float* __restrict__ WqB, const float* __restrict__ WkB) {
    const int u = blockIdx.x * blockDim.x + threadIdx.x;
    const float* src;
    float* dst;
    int i;
    if (u < 2 * N8X) {
        const int idx = u >> 19;          // N8X = 2^19
        i = u & (N8X - 1);
        src = idx ? mB : mA;
        dst = g_x[idx];
    } else {
        const int v = u - 2 * N8X;
        if (v >= 4 * N8W) return;
        const int idx = v >> 15;          // N8W = 2^15
        i = v & (N8W - 1);
        src = (idx == 0) ? WqA : (idx == 1) ? WkA : (idx == 2) ? WqB : WkB;
        dst = g_w[idx];
    }
    const float4 v0 = ((const float4*)src)[2 * i];
    const float4 v1 = ((const float4*)src)[2 * i + 1];
    uint4 o0, o1;
    o0.x = f2tf32(v0.x); o0.y = f2tf32(v1.x);
    o0.z = f2tf32(v0.y); o0.w = f2tf32(v1.y);
    o1.x = f2tf32(v0.z); o1.y = f2tf32(v1.z);
    o1.z = f2tf32(v0.w); o1.w = f2tf32(v1.w);
    ((uint4*)dst)[2 * i]     = o0;
    ((uint4*)dst)[2 * i + 1] = o1;
}

__device__ __forceinline__ int permcol(int x) {
    const int r = x & 7, base = x & ~7;
    return base + ((r < 4) ? 2 * r : 2 * (r - 4) + 1);
}

// ---------------- projections: q/k = x @ W^T + b ----------------
__global__ void __launch_bounds__(256, 2) proj_mma(
    const float* __restrict__ bqA, const float* __restrict__ bkA,
    const float* __restrict__ bqB, const float* __restrict__ bkB) {
    const int cc = blockIdx.z;
    const int m0 = blockIdx.y * 128, n0 = blockIdx.x * 128;
    const float* bias = (cc == 0) ? bqA : (cc == 1) ? bkA : (cc == 2) ? bqB : bkB;

    float acc[4][4][4];
    gemm_core(g_x[cc >> 1], g_w[cc], m0, n0, acc);

    const int lane = threadIdx.x & 31, wid = threadIdx.x >> 5;
    const int wm = (wid & 1) * 64, wn = (wid >> 1) * 32;
    const int g = lane >> 2, c2 = (lane & 3) * 2;
    float* out = g_p[cc];
#pragma unroll
    for (int nt = 0; nt < 4; nt++) {
        const int n = n0 + wn + nt * 8 + c2;
        const float bv0 = __ldg(&bias[n]);
        const float bv1 = __ldg(&bias[n + 1]);
        const int p0 = permcol(n);       // output cols stored K-permuted
        const int p1 = permcol(n + 1);   // so score GEMM loads LDS.64 too
#pragma unroll
        for (int mt = 0; mt < 4; mt++) {
#pragma unroll
            for (int h = 0; h < 2; h++) {
                const int m = m0 + wm + mt * 16 + h * 8 + g;
                float* row = out + (size_t)m * EE;
                ((uint32_t*)row)[p0] = f2tf32(acc[mt][nt][2 * h] + bv0);
                ((uint32_t*)row)[p1] = f2tf32(acc[mt][nt][2 * h + 1] + bv1);
            }
        }
    }
}

// ---------------- scores: S = q @ k^T * inv_scale ----------------
__global__ void __launch_bounds__(256, 2) score_mma(float scale) {
    const int z = blockIdx.z, cc = z >> 3, nn = z & 7;
    const int qsel = (cc < 2) ? 0 : 2;
    const int ksel = (cc == 0 || cc == 3) ? 1 : 3;
    const size_t off = (size_t)nn * LL * EE;
    const int m0 = blockIdx.y * 128, n0 = blockIdx.x * 128;

    float acc[4][4][4];
    gemm_core(g_p[qsel] + off, g_p[ksel] + off, m0, n0, acc);

    const int lane = threadIdx.x & 31, wid = threadIdx.x >> 5;
    const int wm = (wid & 1) * 64, wn = (wid >> 1) * 32;
    const int g = lane >> 2, c2 = (lane & 3) * 2;
    float* out = g_scores[z];
#pragma unroll
    for (int mt = 0; mt < 4; mt++) {
#pragma unroll
        for (int h = 0; h < 2; h++) {
            const int m = m0 + wm + mt * 16 + h * 8 + g;
            float* row = out + (size_t)m * LL;
#pragma unroll
            for (int nt = 0; nt < 4; nt++) {
                float2 v;
                v.x = acc[mt][nt][2 * h] * scale;
                v.y = acc[mt][nt][2 * h + 1] * scale;
                *(float2*)&row[n0 + wn + nt * 8 + c2] = v;
            }
        }
    }
}

// ---------------- block reductions ----------------
__device__ __forceinline__ float blockReduceMax(float v, float* red) {
#pragma unroll
    for (int o = 16; o > 0; o >>= 1) v = fmaxf(v, __shfl_xor_sync(0xffffffffu, v, o));
    const int w = threadIdx.x >> 5;
    if ((threadIdx.x & 31) == 0) red[w] = v;
    __syncthreads();
    if (threadIdx.x < 8) {
        float t = red[threadIdx.x];
#pragma unroll
        for (int o = 4; o > 0; o >>= 1) t = fmaxf(t, __shfl_xor_sync(0xffu, t, o));
        if (threadIdx.x == 0) red[0] = t;
    }
    __syncthreads();
    v = red[0];
    __syncthreads();
    return v;
}
__device__ __forceinline__ float blockReduceSum(float v, float* red) {
#pragma unroll
    for (int o = 16; o > 0; o >>= 1) v += __shfl_xor_sync(0xffffffffu, v, o);
    const int w = threadIdx.x >> 5;
    if ((threadIdx.x & 31) == 0) red[w] = v;
    __syncthreads();
    if (threadIdx.x < 8) {
        float t = red[threadIdx.x];
#pragma unroll
        for (int o = 4; o > 0; o >>= 1) t += __shfl_xor_sync(0xffu, t, o);
        if (threadIdx.x == 0) red[0] = t;
    }
    __syncthreads();
    v = red[0];
    __syncthreads();
    return v;
}

// ---------------- softmax + mean over N, write [2048,2048] ----------------
__global__ void __launch_bounds__(256) softmax_kernel(float* __restrict__ out) {
    const int q = blockIdx.x;
    const int c = blockIdx.y;
    const int tid = threadIdx.x;
    __shared__ float red[8];

    float acc0 = 0.f, acc1 = 0.f, acc2 = 0.f, acc3 = 0.f;
    for (int n = 0; n < NB; n++) {
        const float* row = g_scores[c * 8 + n] + (size_t)q * LL;
        const float4 s = *(const float4*)&row[tid * 4];
        float m = fmaxf(fmaxf(s.x, s.y), fmaxf(s.z, s.w));
        m = blockReduceMax(m, red);
        const float e0 = __expf(s.x - m);
        const float e1 = __expf(s.y - m);
        const float e2 = __expf(s.z - m);
        const float e3 = __expf(s.w - m);
        float sum = e0 + e1 + e2 + e3;
        sum = blockReduceSum(sum, red);
        const float r = 1.0f / sum;
        acc0 += e0 * r; acc1 += e1 * r; acc2 += e2 * r; acc3 += e3 * r;
    }
    const int rowBase = (c >= 2) ? 1024 : 0;
    const int colBase = (c == 1 || c == 3) ? 1024 : 0;
    float4 o;
    o.x = acc0 * 0.125f; o.y = acc1 * 0.125f;
    o.z = acc2 * 0.125f; o.w = acc3 * 0.125f;
    *(float4*)&out[(size_t)(rowBase + q) * 2048 + colBase + tid * 4] = o;
}

// ---------------- launch ----------------
extern "C" void kernel_launch(void* const* d_in, const int* in_sizes, int n_in,
                              void* d_out, int out_size) {
    (void)in_sizes; (void)n_in; (void)out_size;
    const float* mA  = (const float*)d_in[0];
    const float* mB  = (const float*)d_in[1];
    const float* WqA = (const float*)d_in[2];
    const float* bqA = (const float*)d_in[3];
    const float* WkA = (const float*)d_in[4];
    const float* bkA = (const float*)d_in[5];
    const float* WqB = (const float*)d_in[6];
    const float* bqB = (const float*)d_in[7];
    const float* WkB = (const float*)d_in[8];
    const float* bkB = (const float*)d_in[9];
    float* out = (float*)d_out;

    static bool attr_done = false;
    if (!attr_done) {
        cudaFuncSetAttribute(proj_mma,  cudaFuncAttributeMaxDynamicSharedMemorySize, SMEM_SZ);
        cudaFuncSetAttribute(score_mma, cudaFuncAttributeMaxDynamicSharedMemorySize, SMEM_SZ);
        attr_done = true;
    }

    const float inv_scale = 1.0f / (4.0f * sqrtf(512.0f));

    // one fused convert launch (also makes ncu -s 5 land on score_mma)
    const int units = 2 * N8X + 4 * N8W;   // 1179648
    convert_all<<<(units + 255) / 256, 256>>>(mA, mB, WqA, WkA, WqB, WkB);

    // projections: M=8192 (64 tiles), N=512 (4 tiles), 4 combos
    proj_mma<<<dim3(4, 64, 4), 256, SMEM_SZ>>>(bqA, bkA, bqB, bkB);

    // scores: 32 GEMMs of 1024x1024 -> 8x8 tiles each
    score_mma<<<dim3(8, 8, 32), 256, SMEM_SZ>>>(inv_scale);

    // softmax + mean
    softmax_kernel<<<dim3(LL, 4), 256>>>(out);
}